// round 8
// baseline (speedup 1.0000x reference)
#include <cuda_runtime.h>
#include <cstdint>
#include <math.h>

// Problem constants
constexpr int B_  = 4;
constexpr int S_  = 2048;
constexpr int D_  = 1024;
constexpr int H_  = 16;
constexpr int DK_ = 64;
constexpr int M_  = B_ * S_;   // 8192

// Scratch (device globals — no allocation allowed)
__device__ float g_q[(size_t)B_ * H_ * S_ * DK_];   // [B,H,S,DK]
__device__ float g_k[(size_t)B_ * H_ * S_ * DK_];
__device__ float g_v[(size_t)B_ * H_ * S_ * DK_];
__device__ float g_ctx[(size_t)B_ * S_ * D_];       // [B,S,D]

// ---------------------------------------------------------------------------
// tf32 / async helpers (non-suffixed PTX: works under generic sm_103 target)
// ---------------------------------------------------------------------------
__device__ __forceinline__ uint32_t f2tf32(float f) {
    uint32_t r;
    asm("cvt.rna.tf32.f32 %0, %1;" : "=r"(r) : "f"(f));
    return r;
}

__device__ __forceinline__ void mma_tf32_16n8k8(float* c, const uint32_t* a,
                                                uint32_t b0, uint32_t b1) {
    asm volatile(
        "mma.sync.aligned.m16n8k8.row.col.f32.tf32.tf32.f32 "
        "{%0,%1,%2,%3}, {%4,%5,%6,%7}, {%8,%9}, {%0,%1,%2,%3};"
        : "+f"(c[0]), "+f"(c[1]), "+f"(c[2]), "+f"(c[3])
        : "r"(a[0]), "r"(a[1]), "r"(a[2]), "r"(a[3]), "r"(b0), "r"(b1));
}

__device__ __forceinline__ uint32_t smem_u32(const void* p) {
    uint32_t a;
    asm("{ .reg .u64 t; cvta.to.shared.u64 t, %1; cvt.u32.u64 %0, t; }"
        : "=r"(a) : "l"(p));
    return a;
}
__device__ __forceinline__ void cp_async16(uint32_t saddr, const void* g) {
    asm volatile("cp.async.ca.shared.global [%0], [%1], 16;"
                 :: "r"(saddr), "l"(g));
}
#define CP_COMMIT() asm volatile("cp.async.commit_group;" ::: "memory")
#define CP_WAIT0()  asm volatile("cp.async.wait_group 0;" ::: "memory")
#define CP_WAIT1()  asm volatile("cp.async.wait_group 1;" ::: "memory")

// ---------------------------------------------------------------------------
// TF32 tensor-core GEMM v2: Y[M,N] = X @ W^T + bias
// BM=BN=128, BK=16, 256 threads, 3-stage cp.async pipeline (raw fp32 in
// smem, RNA tf32 conversion at fragment load -> numerically identical to v1).
// which = which_base + blockIdx.z:
//   0/1/2 -> g_q/g_k/g_v split-head [B,H,S,DK];  3 -> read g_ctx, write dst.
// ---------------------------------------------------------------------------
constexpr int BK  = 16;
constexpr int LDA = 20;   // padded row stride; 80B rows keep 16B alignment
constexpr int GSTAGE = 128 * LDA;          // floats per tensor per stage
constexpr int GSMEM = 3 * 2 * GSTAGE * 4;  // 61440 B dynamic

__global__ __launch_bounds__(256, 2) void gemm_tf32(
    const float* __restrict__ X,
    const float* __restrict__ W0, const float* __restrict__ W1,
    const float* __restrict__ W2,
    const float* __restrict__ b0p, const float* __restrict__ b1p,
    const float* __restrict__ b2p,
    float* __restrict__ dst, int which_base)
{
    extern __shared__ float gsm[];
    // layout: [stage][A(128*LDA) | B(128*LDA)]
    const uint32_t sbase = smem_u32(gsm);

    const int z = blockIdx.z;
    const int which = which_base + z;
    const float* W    = (z == 0) ? W0 : (z == 1) ? W1 : W2;
    const float* bias = (z == 0) ? b0p : (z == 1) ? b1p : b2p;

    const int tid = threadIdx.x;
    const int wid = tid >> 5;
    const int lane = tid & 31;
    const int m0 = blockIdx.y * 128;
    const int n0 = blockIdx.x * 128;
    const int warp_m = (wid & 3) * 32;
    const int warp_n = (wid >> 2) * 64;

    const float* Xin = (which == 3) ? (const float*)g_ctx : X;
    const float* gA = Xin + (size_t)m0 * D_;
    const float* gB = W + (size_t)n0 * D_;

    // Fill mapping: 512 float4 per tensor per stage; thread does 2 each.
    const int fr0 = tid >> 1;            // rows tid/2 and tid/2+... use f-index
    (void)fr0;

    auto fill = [&](int st, int t) {
#pragma unroll
        for (int i = 0; i < 2; i++) {
            int f = tid + i * 256;        // 0..511
            int row = f >> 2;             // 0..127
            int q4 = (f & 3) * 4;         // 0,4,8,12
            uint32_t sa = sbase + (uint32_t)(st * 2 * GSTAGE + row * LDA + q4) * 4;
            uint32_t sb = sa + (uint32_t)GSTAGE * 4;
            cp_async16(sa, gA + (size_t)row * D_ + t * BK + q4);
            cp_async16(sb, gB + (size_t)row * D_ + t * BK + q4);
        }
        CP_COMMIT();
    };

    float acc[2][8][4];
#pragma unroll
    for (int i = 0; i < 2; i++)
#pragma unroll
        for (int j = 0; j < 8; j++)
#pragma unroll
            for (int r = 0; r < 4; r++) acc[i][j][r] = 0.f;

    constexpr int T = D_ / BK;   // 64
    fill(0, 0);
    fill(1, 1);

    const int r8 = lane >> 2;
    const int c4 = lane & 3;

    int st = 0;
    for (int t = 0; t < T; t++) {
        if (t < T - 1) { CP_WAIT1(); } else { CP_WAIT0(); }
        __syncthreads();
        if (t + 2 < T) {
            int st2 = st + 2; if (st2 >= 3) st2 -= 3;
            fill(st2, t + 2);
        }

        const float* Af = gsm + st * 2 * GSTAGE;
        const float* Bf = Af + GSTAGE;

#pragma unroll
        for (int ks = 0; ks < 2; ks++) {
            const int kk = ks * 8;
            uint32_t a[2][4], b[8][2];
#pragma unroll
            for (int im = 0; im < 2; im++) {
                int mr = warp_m + 16 * im + r8;
                a[im][0] = f2tf32(Af[mr * LDA + kk + c4]);
                a[im][1] = f2tf32(Af[(mr + 8) * LDA + kk + c4]);
                a[im][2] = f2tf32(Af[mr * LDA + kk + c4 + 4]);
                a[im][3] = f2tf32(Af[(mr + 8) * LDA + kk + c4 + 4]);
            }
#pragma unroll
            for (int jn = 0; jn < 8; jn++) {
                int nr = warp_n + 8 * jn + r8;
                b[jn][0] = f2tf32(Bf[nr * LDA + kk + c4]);
                b[jn][1] = f2tf32(Bf[nr * LDA + kk + c4 + 4]);
            }
#pragma unroll
            for (int im = 0; im < 2; im++)
#pragma unroll
                for (int jn = 0; jn < 8; jn++)
                    mma_tf32_16n8k8(acc[im][jn], a[im], b[jn][0], b[jn][1]);
        }

        if (++st == 3) st = 0;
    }

    float* sh_out = (which == 0) ? g_q : (which == 1) ? g_k
                  : (which == 2) ? g_v : dst;
    const int c2 = (lane & 3) * 2;
#pragma unroll
    for (int im = 0; im < 2; im++) {
#pragma unroll
        for (int jn = 0; jn < 8; jn++) {
            int n = n0 + warp_n + 8 * jn + c2;
            float bx = bias[n], by = bias[n + 1];
            int mA = m0 + warp_m + 16 * im + r8;
            int mB = mA + 8;
            float2 v0 = make_float2(acc[im][jn][0] + bx, acc[im][jn][1] + by);
            float2 v1 = make_float2(acc[im][jn][2] + bx, acc[im][jn][3] + by);
            if (which < 3) {
                int h = n >> 6, dk = n & 63;
                int bA = mA >> 11, sA = mA & (S_ - 1);
                int bB = mB >> 11, sB = mB & (S_ - 1);
                *(float2*)&sh_out[(((size_t)(bA * H_ + h) * S_ + sA) << 6) + dk] = v0;
                *(float2*)&sh_out[(((size_t)(bB * H_ + h) * S_ + sB) << 6) + dk] = v1;
            } else {
                *(float2*)&sh_out[(size_t)mA * D_ + n] = v0;
                *(float2*)&sh_out[(size_t)mB * D_ + n] = v1;
            }
        }
    }
}

// ---------------------------------------------------------------------------
// Flash attention v3 (tf32 mma.sync + cp.async double-buffered K/V).
// UNCHANGED from R7 (proven: 515us, rel_err component validated).
// ---------------------------------------------------------------------------
constexpr int LDK2 = 68;
constexpr int LDV2 = 72;
constexpr int LDP2 = 68;
constexpr int FSMEM = (2 * 64 * LDK2 + 2 * 64 * LDV2 + 256 * LDP2) * 4; // 141312

__global__ __launch_bounds__(256, 1) void flash_tf32()
{
    extern __shared__ float smf[];
    float* sKf = smf;
    float* sVf = smf + 2 * 64 * LDK2;
    uint32_t* sP = (uint32_t*)(smf + 2 * 64 * LDK2 + 2 * 64 * LDV2);

    const uint32_t skb = smem_u32(sKf);
    const uint32_t svb = smem_u32(sVf);

    const int tid = threadIdx.x;
    const int wid = tid >> 5;
    const int lane = tid & 31;
    const int r8 = lane >> 2;
    const int c4 = lane & 3;

    const int q0 = blockIdx.x * 256;
    const int h = blockIdx.y;
    const int b = blockIdx.z;
    const size_t base = (size_t)(b * H_ + h) * S_ * DK_;
    const float* qg = g_q + base;
    const float* kg = g_k + base;
    const float* vg = g_v + base;

    const int wr = wid * 32;

    uint32_t aq[2][8][4];
#pragma unroll
    for (int t = 0; t < 2; t++) {
        int row0 = q0 + wr + 16 * t + r8;
        int row1 = row0 + 8;
#pragma unroll
        for (int kk = 0; kk < 8; kk++) {
            int d0 = kk * 8 + c4;
            aq[t][kk][0] = f2tf32(qg[(size_t)row0 * DK_ + d0] * 0.125f);
            aq[t][kk][1] = f2tf32(qg[(size_t)row1 * DK_ + d0] * 0.125f);
            aq[t][kk][2] = f2tf32(qg[(size_t)row0 * DK_ + d0 + 4] * 0.125f);
            aq[t][kk][3] = f2tf32(qg[(size_t)row1 * DK_ + d0 + 4] * 0.125f);
        }
    }

    float mrow[2][2], lrow[2][2];
    float o0[8][4], o1[8][4];
#pragma unroll
    for (int t = 0; t < 2; t++) {
        mrow[t][0] = mrow[t][1] = -1e30f;
        lrow[t][0] = lrow[t][1] = 0.f;
    }
#pragma unroll
    for (int j = 0; j < 8; j++)
#pragma unroll
        for (int r = 0; r < 4; r++) { o0[j][r] = 0.f; o1[j][r] = 0.f; }

    const int prow0 = wr + r8;
    const int prow1 = wr + 16 + r8;

    const int frow0 = tid >> 4;
    const int fcc = (tid & 15) * 4;

    auto issue_chunk = [&](int kb, int st) {
#pragma unroll
        for (int i = 0; i < 4; i++) {
            int row = frow0 + i * 16;
            const float* kp = &kg[(size_t)(kb + row) * DK_ + fcc];
            const float* vp = &vg[(size_t)(kb + row) * DK_ + fcc];
            cp_async16(skb + (uint32_t)(st * 64 * LDK2 + row * LDK2 + fcc) * 4, kp);
            cp_async16(svb + (uint32_t)(st * 64 * LDV2 + row * LDV2 + fcc) * 4, vp);
        }
        CP_COMMIT();
    };

    issue_chunk(0, 0);

    for (int c = 0; c < S_ / 64; c++) {
        const int st = c & 1;
        CP_WAIT0();
        __syncthreads();
        if (c + 1 < S_ / 64) issue_chunk((c + 1) * 64, st ^ 1);

        const float* sKc = sKf + st * 64 * LDK2;
        const float* sVc = sVf + st * 64 * LDV2;

        float s0[8][4], s1[8][4];
#pragma unroll
        for (int j = 0; j < 8; j++)
#pragma unroll
            for (int r = 0; r < 4; r++) { s0[j][r] = 0.f; s1[j][r] = 0.f; }

#pragma unroll
        for (int kk = 0; kk < 8; kk++) {
#pragma unroll
            for (int jn = 0; jn < 8; jn++) {
                const float* kr = &sKc[(8 * jn + r8) * LDK2 + kk * 8 + c4];
                uint32_t b0 = f2tf32(kr[0]);
                uint32_t b1 = f2tf32(kr[4]);
                mma_tf32_16n8k8(s0[jn], aq[0][kk], b0, b1);
                mma_tf32_16n8k8(s1[jn], aq[1][kk], b0, b1);
            }
        }

#pragma unroll
        for (int t = 0; t < 2; t++) {
            float (*s)[4] = (t == 0) ? s0 : s1;
            float (*o)[4] = (t == 0) ? o0 : o1;
            float mx0 = -1e30f, mx1 = -1e30f;
#pragma unroll
            for (int jn = 0; jn < 8; jn++) {
                mx0 = fmaxf(mx0, fmaxf(s[jn][0], s[jn][1]));
                mx1 = fmaxf(mx1, fmaxf(s[jn][2], s[jn][3]));
            }
            mx0 = fmaxf(mx0, __shfl_xor_sync(0xffffffffu, mx0, 1));
            mx0 = fmaxf(mx0, __shfl_xor_sync(0xffffffffu, mx0, 2));
            mx1 = fmaxf(mx1, __shfl_xor_sync(0xffffffffu, mx1, 1));
            mx1 = fmaxf(mx1, __shfl_xor_sync(0xffffffffu, mx1, 2));
            float mn0 = fmaxf(mrow[t][0], mx0), mn1 = fmaxf(mrow[t][1], mx1);
            float alpha0 = __expf(mrow[t][0] - mn0);
            float alpha1 = __expf(mrow[t][1] - mn1);
            float sum0 = 0.f, sum1 = 0.f;
#pragma unroll
            for (int jn = 0; jn < 8; jn++) {
                s[jn][0] = __expf(s[jn][0] - mn0);
                s[jn][1] = __expf(s[jn][1] - mn0);
                s[jn][2] = __expf(s[jn][2] - mn1);
                s[jn][3] = __expf(s[jn][3] - mn1);
                sum0 += s[jn][0] + s[jn][1];
                sum1 += s[jn][2] + s[jn][3];
            }
            sum0 += __shfl_xor_sync(0xffffffffu, sum0, 1);
            sum0 += __shfl_xor_sync(0xffffffffu, sum0, 2);
            sum1 += __shfl_xor_sync(0xffffffffu, sum1, 1);
            sum1 += __shfl_xor_sync(0xffffffffu, sum1, 2);
            lrow[t][0] = lrow[t][0] * alpha0 + sum0;
            lrow[t][1] = lrow[t][1] * alpha1 + sum1;
            mrow[t][0] = mn0;
            mrow[t][1] = mn1;
#pragma unroll
            for (int jn = 0; jn < 8; jn++) {
                o[jn][0] *= alpha0; o[jn][1] *= alpha0;
                o[jn][2] *= alpha1; o[jn][3] *= alpha1;
            }
            int pr = (t == 0) ? prow0 : prow1;
#pragma unroll
            for (int jn = 0; jn < 8; jn++) {
                uint32_t* p0 = &sP[pr * LDP2 + 8 * jn + 2 * c4];
                p0[0] = f2tf32(s[jn][0]);
                p0[1] = f2tf32(s[jn][1]);
                uint32_t* p1 = &sP[(pr + 8) * LDP2 + 8 * jn + 2 * c4];
                p1[0] = f2tf32(s[jn][2]);
                p1[1] = f2tf32(s[jn][3]);
            }
        }
        __syncwarp();

#pragma unroll
        for (int kk = 0; kk < 8; kk++) {
            uint32_t ap0[4], ap1[4];
            ap0[0] = sP[prow0 * LDP2 + kk * 8 + c4];
            ap0[1] = sP[(prow0 + 8) * LDP2 + kk * 8 + c4];
            ap0[2] = sP[prow0 * LDP2 + kk * 8 + c4 + 4];
            ap0[3] = sP[(prow0 + 8) * LDP2 + kk * 8 + c4 + 4];
            ap1[0] = sP[prow1 * LDP2 + kk * 8 + c4];
            ap1[1] = sP[(prow1 + 8) * LDP2 + kk * 8 + c4];
            ap1[2] = sP[prow1 * LDP2 + kk * 8 + c4 + 4];
            ap1[3] = sP[(prow1 + 8) * LDP2 + kk * 8 + c4 + 4];
#pragma unroll
            for (int jn = 0; jn < 8; jn++) {
                uint32_t b0 = f2tf32(sVc[(kk * 8 + c4) * LDV2 + 8 * jn + r8]);
                uint32_t b1 = f2tf32(sVc[(kk * 8 + c4 + 4) * LDV2 + 8 * jn + r8]);
                mma_tf32_16n8k8(o0[jn], ap0, b0, b1);
                mma_tf32_16n8k8(o1[jn], ap1, b0, b1);
            }
        }
        __syncwarp();
    }

#pragma unroll
    for (int t = 0; t < 2; t++) {
        float (*o)[4] = (t == 0) ? o0 : o1;
        float inv0 = 1.0f / lrow[t][0], inv1 = 1.0f / lrow[t][1];
        int row0 = q0 + wr + 16 * t + r8;
        int row1 = row0 + 8;
        size_t g0 = ((size_t)b * S_ + row0) * D_ + h * DK_;
        size_t g1 = ((size_t)b * S_ + row1) * D_ + h * DK_;
#pragma unroll
        for (int jn = 0; jn < 8; jn++) {
            int col = 8 * jn + 2 * c4;
            *(float2*)&g_ctx[g0 + col] = make_float2(o[jn][0] * inv0, o[jn][1] * inv0);
            *(float2*)&g_ctx[g1 + col] = make_float2(o[jn][2] * inv1, o[jn][3] * inv1);
        }
    }
}

// ---------------------------------------------------------------------------
// Launch
// ---------------------------------------------------------------------------
extern "C" void kernel_launch(void* const* d_in, const int* in_sizes, int n_in,
                              void* d_out, int out_size)
{
    const float* Q  = (const float*)d_in[0];
    const float* K  = (const float*)d_in[1];
    const float* V  = (const float*)d_in[2];
    const float* Wq = (const float*)d_in[3];
    const float* bq = (const float*)d_in[4];
    const float* Wk = (const float*)d_in[5];
    const float* bk = (const float*)d_in[6];
    const float* Wv = (const float*)d_in[7];
    const float* bv = (const float*)d_in[8];
    const float* Wo = (const float*)d_in[9];
    const float* bo = (const float*)d_in[10];
    float* out = (float*)d_out;

    cudaFuncSetAttribute(gemm_tf32,
                         cudaFuncAttributeMaxDynamicSharedMemorySize, GSMEM);
    cudaFuncSetAttribute(flash_tf32,
                         cudaFuncAttributeMaxDynamicSharedMemorySize, FSMEM);

    // NOTE: Q/K/V projections fused into one launch (gridDim.z selects which).
    // Inputs X differ per z? No — X is Q vs K vs V... they differ!
    // Wait: z=0 uses Q, z=1 uses K, z=2 uses V. Handle by passing all three
    // X pointers? gemm reads Xin = X for which<3 — so pass per-z X below.
    // We launch the fused kernel once per X is WRONG; instead we pass Q,K,V
    // and select inside. For simplicity and correctness, X selection is
    // folded into the W-slot trick: launch with X=Q..., but z=1 needs K.
    // => dedicated z-indexed launches kept separate for X, fused via 3D grid
    //    is only valid because X depends on z too. We pass Q as X and rely on
    //    kernel-side selection? It cannot see K/V pointers.
    // Resolution: pass Q,K,V through the three W-style slots of a second
    // parameter set is overkill — simply launch the fused kernel with all
    // three inputs via const arrays:
    // (Implemented: gemm reads Xsel from (z==0?X:...) using W1/W2 slots for
    //  K and V inputs when which_base == 0 is NOT possible with current
    //  signature; so we keep THREE separate X pointers by reusing b-slots.)
    // -- Final: we launch qkv with X=Q and pass K,V via extra launches below.

    dim3 ggrid(D_ / 128, M_ / 128, 1);   // (8, 64)
    // Three separate projection launches (X differs per projection; the
    // z-fusion applies only to W/bias selection, so keep z=1 per launch).
    gemm_tf32<<<dim3(8, 64, 1), 256, GSMEM>>>(Q, Wq, Wq, Wq, bq, bq, bq,
                                              nullptr, 0);
    gemm_tf32<<<dim3(8, 64, 1), 256, GSMEM>>>(K, Wk, Wk, Wk, bk, bk, bk,
                                              nullptr, 1);
    gemm_tf32<<<dim3(8, 64, 1), 256, GSMEM>>>(V, Wv, Wv, Wv, bv, bv, bv,
                                              nullptr, 2);

    flash_tf32<<<dim3(S_ / 256, H_, B_), 256, FSMEM>>>();

    gemm_tf32<<<dim3(8, 64, 1), 256, GSMEM>>>(nullptr, Wo, Wo, Wo, bo, bo, bo,
                                              out, 3);
}

// round 9
// speedup vs baseline: 1.0328x; 1.0328x over previous
#include <cuda_runtime.h>
#include <cstdint>
#include <math.h>

// Problem constants
constexpr int B_  = 4;
constexpr int S_  = 2048;
constexpr int D_  = 1024;
constexpr int H_  = 16;
constexpr int DK_ = 64;
constexpr int M_  = B_ * S_;   // 8192

// Scratch (device globals — no allocation allowed)
__device__ float g_q[(size_t)B_ * H_ * S_ * DK_];   // [B,H,S,DK]
__device__ float g_k[(size_t)B_ * H_ * S_ * DK_];
__device__ float g_v[(size_t)B_ * H_ * S_ * DK_];
__device__ float g_ctx[(size_t)B_ * S_ * D_];       // [B,S,D]

// ---------------------------------------------------------------------------
// tf32 / async helpers (non-suffixed PTX: works under generic sm_103 target)
// ---------------------------------------------------------------------------
__device__ __forceinline__ uint32_t f2tf32(float f) {
    uint32_t r;
    asm("cvt.rna.tf32.f32 %0, %1;" : "=r"(r) : "f"(f));
    return r;
}

__device__ __forceinline__ void mma_tf32_16n8k8(float* c, const uint32_t* a,
                                                uint32_t b0, uint32_t b1) {
    asm volatile(
        "mma.sync.aligned.m16n8k8.row.col.f32.tf32.tf32.f32 "
        "{%0,%1,%2,%3}, {%4,%5,%6,%7}, {%8,%9}, {%0,%1,%2,%3};"
        : "+f"(c[0]), "+f"(c[1]), "+f"(c[2]), "+f"(c[3])
        : "r"(a[0]), "r"(a[1]), "r"(a[2]), "r"(a[3]), "r"(b0), "r"(b1));
}

__device__ __forceinline__ uint32_t smem_u32(const void* p) {
    uint32_t a;
    asm("{ .reg .u64 t; cvta.to.shared.u64 t, %1; cvt.u32.u64 %0, t; }"
        : "=r"(a) : "l"(p));
    return a;
}
__device__ __forceinline__ void cp_async16(uint32_t saddr, const void* g) {
    asm volatile("cp.async.ca.shared.global [%0], [%1], 16;"
                 :: "r"(saddr), "l"(g));
}
#define CP_COMMIT() asm volatile("cp.async.commit_group;" ::: "memory")
#define CP_WAIT0()  asm volatile("cp.async.wait_group 0;" ::: "memory")

__device__ __forceinline__ void ldsm_x4(uint32_t& r0, uint32_t& r1,
                                        uint32_t& r2, uint32_t& r3,
                                        uint32_t addr) {
    asm volatile("ldmatrix.sync.aligned.m8n8.x4.shared.b16 {%0,%1,%2,%3}, [%4];"
                 : "=r"(r0), "=r"(r1), "=r"(r2), "=r"(r3) : "r"(addr));
}

// ---------------------------------------------------------------------------
// TF32 tensor-core GEMM: Y[M,N] = X @ W^T + bias
// EXACT R4 version (proven 148us/GEMM). Synchronous reg-prefetch pipeline,
// cvt at STS time.
// ---------------------------------------------------------------------------
constexpr int BK  = 16;
constexpr int LDA = 20;

__global__ __launch_bounds__(256, 2) void gemm_tf32(
    const float* __restrict__ X, const float* __restrict__ W,
    const float* __restrict__ bias, float* __restrict__ dst, int which)
{
    __shared__ uint32_t As[2][128 * LDA];
    __shared__ uint32_t Bs[2][128 * LDA];

    const int tid = threadIdx.x;
    const int wid = tid >> 5;
    const int lane = tid & 31;
    const int m0 = blockIdx.y * 128;
    const int n0 = blockIdx.x * 128;
    const int warp_m = (wid & 3) * 32;
    const int warp_n = (wid >> 2) * 64;

    const float* Xin = (which == 3) ? (const float*)g_ctx : X;

    const int r0 = tid >> 2;
    const int kq = (tid & 3) * 4;

    const float* gA = Xin + (size_t)m0 * D_;
    const float* gB = W + (size_t)n0 * D_;

    float acc[2][8][4];
#pragma unroll
    for (int i = 0; i < 2; i++)
#pragma unroll
        for (int j = 0; j < 8; j++)
#pragma unroll
            for (int r = 0; r < 4; r++) acc[i][j][r] = 0.f;

    float4 pa0, pa1, pb0, pb1;

    auto ldg = [&](int t) {
        const float* a = gA + (size_t)r0 * D_ + t * BK + kq;
        pa0 = *(const float4*)a;
        pa1 = *(const float4*)(a + (size_t)64 * D_);
        const float* b = gB + (size_t)r0 * D_ + t * BK + kq;
        pb0 = *(const float4*)b;
        pb1 = *(const float4*)(b + (size_t)64 * D_);
    };
    auto sts = [&](int s) {
        uint32_t* A = As[s];
        uint32_t* Bsh = Bs[s];
        int o0 = r0 * LDA + kq;
        int o1 = (r0 + 64) * LDA + kq;
        A[o0 + 0] = f2tf32(pa0.x); A[o0 + 1] = f2tf32(pa0.y);
        A[o0 + 2] = f2tf32(pa0.z); A[o0 + 3] = f2tf32(pa0.w);
        A[o1 + 0] = f2tf32(pa1.x); A[o1 + 1] = f2tf32(pa1.y);
        A[o1 + 2] = f2tf32(pa1.z); A[o1 + 3] = f2tf32(pa1.w);
        Bsh[o0 + 0] = f2tf32(pb0.x); Bsh[o0 + 1] = f2tf32(pb0.y);
        Bsh[o0 + 2] = f2tf32(pb0.z); Bsh[o0 + 3] = f2tf32(pb0.w);
        Bsh[o1 + 0] = f2tf32(pb1.x); Bsh[o1 + 1] = f2tf32(pb1.y);
        Bsh[o1 + 2] = f2tf32(pb1.z); Bsh[o1 + 3] = f2tf32(pb1.w);
    };

    ldg(0);
    sts(0);
    __syncthreads();

    const int r8 = lane >> 2;
    const int c4 = lane & 3;

    for (int t = 0; t < D_ / BK; t++) {
        int s = t & 1;
        if (t < D_ / BK - 1) ldg(t + 1);

#pragma unroll
        for (int ks = 0; ks < 2; ks++) {
            const int kk = ks * 8;
            uint32_t a[2][4], b[8][2];
#pragma unroll
            for (int im = 0; im < 2; im++) {
                int mr = warp_m + 16 * im + r8;
                a[im][0] = As[s][mr * LDA + kk + c4];
                a[im][1] = As[s][(mr + 8) * LDA + kk + c4];
                a[im][2] = As[s][mr * LDA + kk + c4 + 4];
                a[im][3] = As[s][(mr + 8) * LDA + kk + c4 + 4];
            }
#pragma unroll
            for (int jn = 0; jn < 8; jn++) {
                int nr = warp_n + 8 * jn + r8;
                b[jn][0] = Bs[s][nr * LDA + kk + c4];
                b[jn][1] = Bs[s][nr * LDA + kk + c4 + 4];
            }
#pragma unroll
            for (int im = 0; im < 2; im++)
#pragma unroll
                for (int jn = 0; jn < 8; jn++)
                    mma_tf32_16n8k8(acc[im][jn], a[im], b[jn][0], b[jn][1]);
        }

        if (t < D_ / BK - 1) sts(s ^ 1);
        __syncthreads();
    }

    float* sh_out = (which == 0) ? g_q : (which == 1) ? g_k
                  : (which == 2) ? g_v : dst;
    const int c2 = (lane & 3) * 2;
#pragma unroll
    for (int im = 0; im < 2; im++) {
#pragma unroll
        for (int jn = 0; jn < 8; jn++) {
            int n = n0 + warp_n + 8 * jn + c2;
            float bx = bias[n], by = bias[n + 1];
            int mA = m0 + warp_m + 16 * im + r8;
            int mB = mA + 8;
            float2 v0 = make_float2(acc[im][jn][0] + bx, acc[im][jn][1] + by);
            float2 v1 = make_float2(acc[im][jn][2] + bx, acc[im][jn][3] + by);
            if (which < 3) {
                int h = n >> 6, dk = n & 63;
                int bA = mA >> 11, sA = mA & (S_ - 1);
                int bB = mB >> 11, sB = mB & (S_ - 1);
                *(float2*)&sh_out[(((size_t)(bA * H_ + h) * S_ + sA) << 6) + dk] = v0;
                *(float2*)&sh_out[(((size_t)(bB * H_ + h) * S_ + sB) << 6) + dk] = v1;
            } else {
                *(float2*)&sh_out[(size_t)mA * D_ + n] = v0;
                *(float2*)&sh_out[(size_t)mB * D_ + n] = v1;
            }
        }
    }
}

// ---------------------------------------------------------------------------
// Flash attention v4: tf32 mma.sync + cp.async double buffer + ldmatrix
// fragment loads for K (B-frags) and P (A-frags). V stays scalar LDS
// (transposed layout incompatible with 16B cp.async fill).
// Identical bits and MMA order as v3 -> rel_err unchanged.
// ---------------------------------------------------------------------------
constexpr int LDK2 = 68;   // 68 % 32 == 4 -> ldmatrix rows conflict-free
constexpr int LDV2 = 72;   // scalar-LDS pattern (8*c4 + r8) bijective
constexpr int LDP2 = 68;   // ldmatrix rows conflict-free
constexpr int FSMEM = (2 * 64 * LDK2 + 2 * 64 * LDV2 + 256 * LDP2) * 4; // 141312

__global__ __launch_bounds__(256, 1) void flash_tf32()
{
    extern __shared__ float smf[];
    float* sKf = smf;
    float* sVf = smf + 2 * 64 * LDK2;
    uint32_t* sP = (uint32_t*)(smf + 2 * 64 * LDK2 + 2 * 64 * LDV2);

    const uint32_t skb = smem_u32(sKf);
    const uint32_t svb = smem_u32(sVf);
    const uint32_t spb = smem_u32(sP);

    const int tid = threadIdx.x;
    const int wid = tid >> 5;
    const int lane = tid & 31;
    const int r8 = lane >> 2;
    const int c4 = lane & 3;

    // ldmatrix lane-address constants: m = lane>>3 (matrix), lr = lane&7 (row)
    const int lm = lane >> 3;
    const int lr7 = lane & 7;
    // K x4: matrices {jn,b0},{jn,b1},{jn+1,b0},{jn+1,b1}
    //   row = 8*(m>>1) + lr ; float col = 4*(m&1)
    const uint32_t laneK =
        (uint32_t)(((8 * (lm >> 1) + lr7) * LDK2 + 4 * (lm & 1)) * 4);
    // P x4 (A-frag): matrices {rows 0-7,c0},{rows 8-15,c0},{rows 0-7,c4},{rows 8-15,c4}
    //   row = 8*(m&1) + lr ; float col = 4*(m>>1)
    const uint32_t laneP =
        (uint32_t)(((8 * (lm & 1) + lr7) * LDP2 + 4 * (lm >> 1)) * 4);

    const int q0 = blockIdx.x * 256;
    const int h = blockIdx.y;
    const int b = blockIdx.z;
    const size_t base = (size_t)(b * H_ + h) * S_ * DK_;
    const float* qg = g_q + base;
    const float* kg = g_k + base;
    const float* vg = g_v + base;

    const int wr = wid * 32;

    uint32_t aq[2][8][4];
#pragma unroll
    for (int t = 0; t < 2; t++) {
        int row0 = q0 + wr + 16 * t + r8;
        int row1 = row0 + 8;
#pragma unroll
        for (int kk = 0; kk < 8; kk++) {
            int d0 = kk * 8 + c4;
            aq[t][kk][0] = f2tf32(qg[(size_t)row0 * DK_ + d0] * 0.125f);
            aq[t][kk][1] = f2tf32(qg[(size_t)row1 * DK_ + d0] * 0.125f);
            aq[t][kk][2] = f2tf32(qg[(size_t)row0 * DK_ + d0 + 4] * 0.125f);
            aq[t][kk][3] = f2tf32(qg[(size_t)row1 * DK_ + d0 + 4] * 0.125f);
        }
    }

    float mrow[2][2], lrow[2][2];
    float o0[8][4], o1[8][4];
#pragma unroll
    for (int t = 0; t < 2; t++) {
        mrow[t][0] = mrow[t][1] = -1e30f;
        lrow[t][0] = lrow[t][1] = 0.f;
    }
#pragma unroll
    for (int j = 0; j < 8; j++)
#pragma unroll
        for (int r = 0; r < 4; r++) { o0[j][r] = 0.f; o1[j][r] = 0.f; }

    const int prow0 = wr + r8;
    const int prow1 = wr + 16 + r8;
    const uint32_t paddr0 = spb + (uint32_t)(wr * LDP2 * 4) + laneP;
    const uint32_t paddr1 = paddr0 + (uint32_t)(16 * LDP2 * 4);

    const int frow0 = tid >> 4;
    const int fcc = (tid & 15) * 4;

    auto issue_chunk = [&](int kb, int st) {
#pragma unroll
        for (int i = 0; i < 4; i++) {
            int row = frow0 + i * 16;
            const float* kp = &kg[(size_t)(kb + row) * DK_ + fcc];
            const float* vp = &vg[(size_t)(kb + row) * DK_ + fcc];
            cp_async16(skb + (uint32_t)(st * 64 * LDK2 + row * LDK2 + fcc) * 4, kp);
            cp_async16(svb + (uint32_t)(st * 64 * LDV2 + row * LDV2 + fcc) * 4, vp);
        }
        CP_COMMIT();
    };

    issue_chunk(0, 0);

    for (int c = 0; c < S_ / 64; c++) {
        const int st = c & 1;
        CP_WAIT0();
        __syncthreads();
        if (c + 1 < S_ / 64) issue_chunk((c + 1) * 64, st ^ 1);

        const float* sVc = sVf + st * 64 * LDV2;
        const uint32_t skc_u = skb + (uint32_t)(st * 64 * LDK2) * 4 + laneK;

        // ---- S = Q K^T via ldmatrix B-frags (one x4 covers 2 jn) ----
        float s0[8][4], s1[8][4];
#pragma unroll
        for (int j = 0; j < 8; j++)
#pragma unroll
            for (int r = 0; r < 4; r++) { s0[j][r] = 0.f; s1[j][r] = 0.f; }

#pragma unroll
        for (int kk = 0; kk < 8; kk++) {
            const uint32_t ka = skc_u + (uint32_t)(kk * 32);
#pragma unroll
            for (int jnp = 0; jnp < 4; jnp++) {
                uint32_t t0, t1, t2, t3;
                ldsm_x4(t0, t1, t2, t3,
                        ka + (uint32_t)(jnp * 16 * LDK2 * 4));
                uint32_t b00 = f2tf32(__uint_as_float(t0));
                uint32_t b01 = f2tf32(__uint_as_float(t1));
                uint32_t b10 = f2tf32(__uint_as_float(t2));
                uint32_t b11 = f2tf32(__uint_as_float(t3));
                mma_tf32_16n8k8(s0[2 * jnp], aq[0][kk], b00, b01);
                mma_tf32_16n8k8(s1[2 * jnp], aq[1][kk], b00, b01);
                mma_tf32_16n8k8(s0[2 * jnp + 1], aq[0][kk], b10, b11);
                mma_tf32_16n8k8(s1[2 * jnp + 1], aq[1][kk], b10, b11);
            }
        }

        // ---- online softmax + stage P, per tile ----
#pragma unroll
        for (int t = 0; t < 2; t++) {
            float (*s)[4] = (t == 0) ? s0 : s1;
            float (*o)[4] = (t == 0) ? o0 : o1;
            float mx0 = -1e30f, mx1 = -1e30f;
#pragma unroll
            for (int jn = 0; jn < 8; jn++) {
                mx0 = fmaxf(mx0, fmaxf(s[jn][0], s[jn][1]));
                mx1 = fmaxf(mx1, fmaxf(s[jn][2], s[jn][3]));
            }
            mx0 = fmaxf(mx0, __shfl_xor_sync(0xffffffffu, mx0, 1));
            mx0 = fmaxf(mx0, __shfl_xor_sync(0xffffffffu, mx0, 2));
            mx1 = fmaxf(mx1, __shfl_xor_sync(0xffffffffu, mx1, 1));
            mx1 = fmaxf(mx1, __shfl_xor_sync(0xffffffffu, mx1, 2));
            float mn0 = fmaxf(mrow[t][0], mx0), mn1 = fmaxf(mrow[t][1], mx1);
            float alpha0 = __expf(mrow[t][0] - mn0);
            float alpha1 = __expf(mrow[t][1] - mn1);
            float sum0 = 0.f, sum1 = 0.f;
#pragma unroll
            for (int jn = 0; jn < 8; jn++) {
                s[jn][0] = __expf(s[jn][0] - mn0);
                s[jn][1] = __expf(s[jn][1] - mn0);
                s[jn][2] = __expf(s[jn][2] - mn1);
                s[jn][3] = __expf(s[jn][3] - mn1);
                sum0 += s[jn][0] + s[jn][1];
                sum1 += s[jn][2] + s[jn][3];
            }
            sum0 += __shfl_xor_sync(0xffffffffu, sum0, 1);
            sum0 += __shfl_xor_sync(0xffffffffu, sum0, 2);
            sum1 += __shfl_xor_sync(0xffffffffu, sum1, 1);
            sum1 += __shfl_xor_sync(0xffffffffu, sum1, 2);
            lrow[t][0] = lrow[t][0] * alpha0 + sum0;
            lrow[t][1] = lrow[t][1] * alpha1 + sum1;
            mrow[t][0] = mn0;
            mrow[t][1] = mn1;
#pragma unroll
            for (int jn = 0; jn < 8; jn++) {
                o[jn][0] *= alpha0; o[jn][1] *= alpha0;
                o[jn][2] *= alpha1; o[jn][3] *= alpha1;
            }
            int pr = (t == 0) ? prow0 : prow1;
#pragma unroll
            for (int jn = 0; jn < 8; jn++) {
                uint32_t* p0 = &sP[pr * LDP2 + 8 * jn + 2 * c4];
                p0[0] = f2tf32(s[jn][0]);
                p0[1] = f2tf32(s[jn][1]);
                uint32_t* p1 = &sP[(pr + 8) * LDP2 + 8 * jn + 2 * c4];
                p1[0] = f2tf32(s[jn][2]);
                p1[1] = f2tf32(s[jn][3]);
            }
        }
        __syncwarp();

        // ---- O += P V (P A-frags via ldmatrix; V scalar) ----
#pragma unroll
        for (int kk = 0; kk < 8; kk++) {
            uint32_t ap0[4], ap1[4];
            ldsm_x4(ap0[0], ap0[1], ap0[2], ap0[3],
                    paddr0 + (uint32_t)(kk * 32));
            ldsm_x4(ap1[0], ap1[1], ap1[2], ap1[3],
                    paddr1 + (uint32_t)(kk * 32));
#pragma unroll
            for (int jn = 0; jn < 8; jn++) {
                uint32_t b0 = f2tf32(sVc[(kk * 8 + c4) * LDV2 + 8 * jn + r8]);
                uint32_t b1 = f2tf32(sVc[(kk * 8 + c4 + 4) * LDV2 + 8 * jn + r8]);
                mma_tf32_16n8k8(o0[jn], ap0, b0, b1);
                mma_tf32_16n8k8(o1[jn], ap1, b0, b1);
            }
        }
        __syncwarp();
    }

#pragma unroll
    for (int t = 0; t < 2; t++) {
        float (*o)[4] = (t == 0) ? o0 : o1;
        float inv0 = 1.0f / lrow[t][0], inv1 = 1.0f / lrow[t][1];
        int row0 = q0 + wr + 16 * t + r8;
        int row1 = row0 + 8;
        size_t g0 = ((size_t)b * S_ + row0) * D_ + h * DK_;
        size_t g1 = ((size_t)b * S_ + row1) * D_ + h * DK_;
#pragma unroll
        for (int jn = 0; jn < 8; jn++) {
            int col = 8 * jn + 2 * c4;
            *(float2*)&g_ctx[g0 + col] = make_float2(o[jn][0] * inv0, o[jn][1] * inv0);
            *(float2*)&g_ctx[g1 + col] = make_float2(o[jn][2] * inv1, o[jn][3] * inv1);
        }
    }
}

// ---------------------------------------------------------------------------
// Launch
// ---------------------------------------------------------------------------
extern "C" void kernel_launch(void* const* d_in, const int* in_sizes, int n_in,
                              void* d_out, int out_size)
{
    const float* Q  = (const float*)d_in[0];
    const float* K  = (const float*)d_in[1];
    const float* V  = (const float*)d_in[2];
    const float* Wq = (const float*)d_in[3];
    const float* bq = (const float*)d_in[4];
    const float* Wk = (const float*)d_in[5];
    const float* bk = (const float*)d_in[6];
    const float* Wv = (const float*)d_in[7];
    const float* bv = (const float*)d_in[8];
    const float* Wo = (const float*)d_in[9];
    const float* bo = (const float*)d_in[10];
    float* out = (float*)d_out;

    cudaFuncSetAttribute(flash_tf32,
                         cudaFuncAttributeMaxDynamicSharedMemorySize, FSMEM);

    dim3 ggrid(D_ / 128, M_ / 128);   // (8, 64)
    gemm_tf32<<<ggrid, 256>>>(Q, Wq, bq, nullptr, 0);
    gemm_tf32<<<ggrid, 256>>>(K, Wk, bk, nullptr, 1);
    gemm_tf32<<<ggrid, 256>>>(V, Wv, bv, nullptr, 2);

    flash_tf32<<<dim3(S_ / 256, H_, B_), 256, FSMEM>>>();

    gemm_tf32<<<ggrid, 256>>>(nullptr, Wo, bo, out, 3);
}

// round 10
// speedup vs baseline: 1.0632x; 1.0294x over previous
#include <cuda_runtime.h>
#include <cstdint>
#include <math.h>

// Problem constants
constexpr int B_  = 4;
constexpr int S_  = 2048;
constexpr int D_  = 1024;
constexpr int H_  = 16;
constexpr int DK_ = 64;
constexpr int M_  = B_ * S_;   // 8192

// Scratch (device globals — no allocation allowed)
// g_q/g_k/g_v hold TF32-PRE-ROUNDED fp32 values (rounded in proj epilogue).
__device__ float g_q[(size_t)B_ * H_ * S_ * DK_];   // [B,H,S,DK]
__device__ float g_k[(size_t)B_ * H_ * S_ * DK_];
__device__ float g_v[(size_t)B_ * H_ * S_ * DK_];
__device__ float g_ctx[(size_t)B_ * S_ * D_];       // [B,S,D]

// ---------------------------------------------------------------------------
// tf32 / async helpers (non-suffixed PTX: works under generic sm_103 target)
// ---------------------------------------------------------------------------
__device__ __forceinline__ uint32_t f2tf32(float f) {
    uint32_t r;
    asm("cvt.rna.tf32.f32 %0, %1;" : "=r"(r) : "f"(f));
    return r;
}

__device__ __forceinline__ void mma_tf32_16n8k8(float* c, const uint32_t* a,
                                                uint32_t b0, uint32_t b1) {
    asm volatile(
        "mma.sync.aligned.m16n8k8.row.col.f32.tf32.tf32.f32 "
        "{%0,%1,%2,%3}, {%4,%5,%6,%7}, {%8,%9}, {%0,%1,%2,%3};"
        : "+f"(c[0]), "+f"(c[1]), "+f"(c[2]), "+f"(c[3])
        : "r"(a[0]), "r"(a[1]), "r"(a[2]), "r"(a[3]), "r"(b0), "r"(b1));
}

__device__ __forceinline__ uint32_t smem_u32(const void* p) {
    uint32_t a;
    asm("{ .reg .u64 t; cvta.to.shared.u64 t, %1; cvt.u32.u64 %0, t; }"
        : "=r"(a) : "l"(p));
    return a;
}
__device__ __forceinline__ void cp_async16(uint32_t saddr, const void* g) {
    asm volatile("cp.async.ca.shared.global [%0], [%1], 16;"
                 :: "r"(saddr), "l"(g));
}
#define CP_COMMIT() asm volatile("cp.async.commit_group;" ::: "memory")
#define CP_WAIT0()  asm volatile("cp.async.wait_group 0;" ::: "memory")

__device__ __forceinline__ void ldsm_x4(uint32_t& r0, uint32_t& r1,
                                        uint32_t& r2, uint32_t& r3,
                                        uint32_t addr) {
    asm volatile("ldmatrix.sync.aligned.m8n8.x4.shared.b16 {%0,%1,%2,%3}, [%4];"
                 : "=r"(r0), "=r"(r1), "=r"(r2), "=r"(r3) : "r"(addr));
}

// ---------------------------------------------------------------------------
// TF32 tensor-core GEMM: Y[M,N] = X @ W^T + bias  (R4 core, proven).
// NEW: for which<3 (Q/K/V projections) the epilogue stores TF32-ROUNDED
// values — flash consumes the bits directly, eliminating its K/V cvts.
// ---------------------------------------------------------------------------
constexpr int BK  = 16;
constexpr int LDA = 20;

__global__ __launch_bounds__(256, 2) void gemm_tf32(
    const float* __restrict__ X, const float* __restrict__ W,
    const float* __restrict__ bias, float* __restrict__ dst, int which)
{
    __shared__ uint32_t As[2][128 * LDA];
    __shared__ uint32_t Bs[2][128 * LDA];

    const int tid = threadIdx.x;
    const int wid = tid >> 5;
    const int lane = tid & 31;
    const int m0 = blockIdx.y * 128;
    const int n0 = blockIdx.x * 128;
    const int warp_m = (wid & 3) * 32;
    const int warp_n = (wid >> 2) * 64;

    const float* Xin = (which == 3) ? (const float*)g_ctx : X;

    const int r0 = tid >> 2;
    const int kq = (tid & 3) * 4;

    const float* gA = Xin + (size_t)m0 * D_;
    const float* gB = W + (size_t)n0 * D_;

    float acc[2][8][4];
#pragma unroll
    for (int i = 0; i < 2; i++)
#pragma unroll
        for (int j = 0; j < 8; j++)
#pragma unroll
            for (int r = 0; r < 4; r++) acc[i][j][r] = 0.f;

    float4 pa0, pa1, pb0, pb1;

    auto ldg = [&](int t) {
        const float* a = gA + (size_t)r0 * D_ + t * BK + kq;
        pa0 = *(const float4*)a;
        pa1 = *(const float4*)(a + (size_t)64 * D_);
        const float* b = gB + (size_t)r0 * D_ + t * BK + kq;
        pb0 = *(const float4*)b;
        pb1 = *(const float4*)(b + (size_t)64 * D_);
    };
    auto sts = [&](int s) {
        uint32_t* A = As[s];
        uint32_t* Bsh = Bs[s];
        int o0 = r0 * LDA + kq;
        int o1 = (r0 + 64) * LDA + kq;
        A[o0 + 0] = f2tf32(pa0.x); A[o0 + 1] = f2tf32(pa0.y);
        A[o0 + 2] = f2tf32(pa0.z); A[o0 + 3] = f2tf32(pa0.w);
        A[o1 + 0] = f2tf32(pa1.x); A[o1 + 1] = f2tf32(pa1.y);
        A[o1 + 2] = f2tf32(pa1.z); A[o1 + 3] = f2tf32(pa1.w);
        Bsh[o0 + 0] = f2tf32(pb0.x); Bsh[o0 + 1] = f2tf32(pb0.y);
        Bsh[o0 + 2] = f2tf32(pb0.z); Bsh[o0 + 3] = f2tf32(pb0.w);
        Bsh[o1 + 0] = f2tf32(pb1.x); Bsh[o1 + 1] = f2tf32(pb1.y);
        Bsh[o1 + 2] = f2tf32(pb1.z); Bsh[o1 + 3] = f2tf32(pb1.w);
    };

    ldg(0);
    sts(0);
    __syncthreads();

    const int r8 = lane >> 2;
    const int c4 = lane & 3;

    for (int t = 0; t < D_ / BK; t++) {
        int s = t & 1;
        if (t < D_ / BK - 1) ldg(t + 1);

#pragma unroll
        for (int ks = 0; ks < 2; ks++) {
            const int kk = ks * 8;
            uint32_t a[2][4], b[8][2];
#pragma unroll
            for (int im = 0; im < 2; im++) {
                int mr = warp_m + 16 * im + r8;
                a[im][0] = As[s][mr * LDA + kk + c4];
                a[im][1] = As[s][(mr + 8) * LDA + kk + c4];
                a[im][2] = As[s][mr * LDA + kk + c4 + 4];
                a[im][3] = As[s][(mr + 8) * LDA + kk + c4 + 4];
            }
#pragma unroll
            for (int jn = 0; jn < 8; jn++) {
                int nr = warp_n + 8 * jn + r8;
                b[jn][0] = Bs[s][nr * LDA + kk + c4];
                b[jn][1] = Bs[s][nr * LDA + kk + c4 + 4];
            }
#pragma unroll
            for (int im = 0; im < 2; im++)
#pragma unroll
                for (int jn = 0; jn < 8; jn++)
                    mma_tf32_16n8k8(acc[im][jn], a[im], b[jn][0], b[jn][1]);
        }

        if (t < D_ / BK - 1) sts(s ^ 1);
        __syncthreads();
    }

    float* sh_out = (which == 0) ? g_q : (which == 1) ? g_k
                  : (which == 2) ? g_v : dst;
    const int c2 = (lane & 3) * 2;
#pragma unroll
    for (int im = 0; im < 2; im++) {
#pragma unroll
        for (int jn = 0; jn < 8; jn++) {
            int n = n0 + warp_n + 8 * jn + c2;
            float bx = bias[n], by = bias[n + 1];
            int mA = m0 + warp_m + 16 * im + r8;
            int mB = mA + 8;
            float2 v0 = make_float2(acc[im][jn][0] + bx, acc[im][jn][1] + by);
            float2 v1 = make_float2(acc[im][jn][2] + bx, acc[im][jn][3] + by);
            if (which < 3) {
                // Pre-round to tf32 HERE (one-time) so flash skips cvts.
                v0.x = __uint_as_float(f2tf32(v0.x));
                v0.y = __uint_as_float(f2tf32(v0.y));
                v1.x = __uint_as_float(f2tf32(v1.x));
                v1.y = __uint_as_float(f2tf32(v1.y));
                int h = n >> 6, dk = n & 63;
                int bA = mA >> 11, sA = mA & (S_ - 1);
                int bB = mB >> 11, sB = mB & (S_ - 1);
                *(float2*)&sh_out[(((size_t)(bA * H_ + h) * S_ + sA) << 6) + dk] = v0;
                *(float2*)&sh_out[(((size_t)(bB * H_ + h) * S_ + sB) << 6) + dk] = v1;
            } else {
                *(float2*)&sh_out[(size_t)mA * D_ + n] = v0;
                *(float2*)&sh_out[(size_t)mB * D_ + n] = v1;
            }
        }
    }
}

// ---------------------------------------------------------------------------
// Flash attention v5: tf32 mma.sync + cp.async + ldmatrix, consuming
// PRE-ROUNDED g_q/g_k/g_v -> zero cvts on the K and V fragment paths.
// tf32(q)*0.125 == tf32(q*0.125) exactly (power-of-2 scale), so Q path is
// also cvt-free. Bitwise-identical MMA operands -> rel_err unchanged.
// ---------------------------------------------------------------------------
constexpr int LDK2 = 68;
constexpr int LDV2 = 72;
constexpr int LDP2 = 68;
constexpr int FSMEM = (2 * 64 * LDK2 + 2 * 64 * LDV2 + 256 * LDP2) * 4; // 141312

__global__ __launch_bounds__(256, 1) void flash_tf32()
{
    extern __shared__ float smf[];
    float* sKf = smf;
    float* sVf = smf + 2 * 64 * LDK2;
    uint32_t* sP = (uint32_t*)(smf + 2 * 64 * LDK2 + 2 * 64 * LDV2);

    const uint32_t skb = smem_u32(sKf);
    const uint32_t svb = smem_u32(sVf);
    const uint32_t spb = smem_u32(sP);

    const int tid = threadIdx.x;
    const int wid = tid >> 5;
    const int lane = tid & 31;
    const int r8 = lane >> 2;
    const int c4 = lane & 3;

    const int lm = lane >> 3;
    const int lr7 = lane & 7;
    const uint32_t laneK =
        (uint32_t)(((8 * (lm >> 1) + lr7) * LDK2 + 4 * (lm & 1)) * 4);
    const uint32_t laneP =
        (uint32_t)(((8 * (lm & 1) + lr7) * LDP2 + 4 * (lm >> 1)) * 4);

    const int q0 = blockIdx.x * 256;
    const int h = blockIdx.y;
    const int b = blockIdx.z;
    const size_t base = (size_t)(b * H_ + h) * S_ * DK_;
    const float* qg = g_q + base;
    const float* kg = g_k + base;
    const float* vg = g_v + base;

    const int wr = wid * 32;

    // Q A-fragments: values pre-rounded; *0.125f is exact -> reinterpret.
    uint32_t aq[2][8][4];
#pragma unroll
    for (int t = 0; t < 2; t++) {
        int row0 = q0 + wr + 16 * t + r8;
        int row1 = row0 + 8;
#pragma unroll
        for (int kk = 0; kk < 8; kk++) {
            int d0 = kk * 8 + c4;
            aq[t][kk][0] = __float_as_uint(qg[(size_t)row0 * DK_ + d0] * 0.125f);
            aq[t][kk][1] = __float_as_uint(qg[(size_t)row1 * DK_ + d0] * 0.125f);
            aq[t][kk][2] = __float_as_uint(qg[(size_t)row0 * DK_ + d0 + 4] * 0.125f);
            aq[t][kk][3] = __float_as_uint(qg[(size_t)row1 * DK_ + d0 + 4] * 0.125f);
        }
    }

    float mrow[2][2], lrow[2][2];
    float o0[8][4], o1[8][4];
#pragma unroll
    for (int t = 0; t < 2; t++) {
        mrow[t][0] = mrow[t][1] = -1e30f;
        lrow[t][0] = lrow[t][1] = 0.f;
    }
#pragma unroll
    for (int j = 0; j < 8; j++)
#pragma unroll
        for (int r = 0; r < 4; r++) { o0[j][r] = 0.f; o1[j][r] = 0.f; }

    const int prow0 = wr + r8;
    const int prow1 = wr + 16 + r8;
    const uint32_t paddr0 = spb + (uint32_t)(wr * LDP2 * 4) + laneP;
    const uint32_t paddr1 = paddr0 + (uint32_t)(16 * LDP2 * 4);

    const int frow0 = tid >> 4;
    const int fcc = (tid & 15) * 4;

    auto issue_chunk = [&](int kb, int st) {
#pragma unroll
        for (int i = 0; i < 4; i++) {
            int row = frow0 + i * 16;
            const float* kp = &kg[(size_t)(kb + row) * DK_ + fcc];
            const float* vp = &vg[(size_t)(kb + row) * DK_ + fcc];
            cp_async16(skb + (uint32_t)(st * 64 * LDK2 + row * LDK2 + fcc) * 4, kp);
            cp_async16(svb + (uint32_t)(st * 64 * LDV2 + row * LDV2 + fcc) * 4, vp);
        }
        CP_COMMIT();
    };

    issue_chunk(0, 0);

    for (int c = 0; c < S_ / 64; c++) {
        const int st = c & 1;
        CP_WAIT0();
        __syncthreads();
        if (c + 1 < S_ / 64) issue_chunk((c + 1) * 64, st ^ 1);

        const float* sVc = sVf + st * 64 * LDV2;
        const uint32_t* sVu = (const uint32_t*)sVc;
        const uint32_t skc_u = skb + (uint32_t)(st * 64 * LDK2) * 4 + laneK;

        // ---- S = Q K^T via ldmatrix B-frags (bits already tf32) ----
        float s0[8][4], s1[8][4];
#pragma unroll
        for (int j = 0; j < 8; j++)
#pragma unroll
            for (int r = 0; r < 4; r++) { s0[j][r] = 0.f; s1[j][r] = 0.f; }

#pragma unroll
        for (int kk = 0; kk < 8; kk++) {
            const uint32_t ka = skc_u + (uint32_t)(kk * 32);
#pragma unroll
            for (int jnp = 0; jnp < 4; jnp++) {
                uint32_t b00, b01, b10, b11;
                ldsm_x4(b00, b01, b10, b11,
                        ka + (uint32_t)(jnp * 16 * LDK2 * 4));
                mma_tf32_16n8k8(s0[2 * jnp], aq[0][kk], b00, b01);
                mma_tf32_16n8k8(s1[2 * jnp], aq[1][kk], b00, b01);
                mma_tf32_16n8k8(s0[2 * jnp + 1], aq[0][kk], b10, b11);
                mma_tf32_16n8k8(s1[2 * jnp + 1], aq[1][kk], b10, b11);
            }
        }

        // ---- online softmax + stage P, per tile ----
#pragma unroll
        for (int t = 0; t < 2; t++) {
            float (*s)[4] = (t == 0) ? s0 : s1;
            float (*o)[4] = (t == 0) ? o0 : o1;
            float mx0 = -1e30f, mx1 = -1e30f;
#pragma unroll
            for (int jn = 0; jn < 8; jn++) {
                mx0 = fmaxf(mx0, fmaxf(s[jn][0], s[jn][1]));
                mx1 = fmaxf(mx1, fmaxf(s[jn][2], s[jn][3]));
            }
            mx0 = fmaxf(mx0, __shfl_xor_sync(0xffffffffu, mx0, 1));
            mx0 = fmaxf(mx0, __shfl_xor_sync(0xffffffffu, mx0, 2));
            mx1 = fmaxf(mx1, __shfl_xor_sync(0xffffffffu, mx1, 1));
            mx1 = fmaxf(mx1, __shfl_xor_sync(0xffffffffu, mx1, 2));
            float mn0 = fmaxf(mrow[t][0], mx0), mn1 = fmaxf(mrow[t][1], mx1);
            float alpha0 = __expf(mrow[t][0] - mn0);
            float alpha1 = __expf(mrow[t][1] - mn1);
            float sum0 = 0.f, sum1 = 0.f;
#pragma unroll
            for (int jn = 0; jn < 8; jn++) {
                s[jn][0] = __expf(s[jn][0] - mn0);
                s[jn][1] = __expf(s[jn][1] - mn0);
                s[jn][2] = __expf(s[jn][2] - mn1);
                s[jn][3] = __expf(s[jn][3] - mn1);
                sum0 += s[jn][0] + s[jn][1];
                sum1 += s[jn][2] + s[jn][3];
            }
            sum0 += __shfl_xor_sync(0xffffffffu, sum0, 1);
            sum0 += __shfl_xor_sync(0xffffffffu, sum0, 2);
            sum1 += __shfl_xor_sync(0xffffffffu, sum1, 1);
            sum1 += __shfl_xor_sync(0xffffffffu, sum1, 2);
            lrow[t][0] = lrow[t][0] * alpha0 + sum0;
            lrow[t][1] = lrow[t][1] * alpha1 + sum1;
            mrow[t][0] = mn0;
            mrow[t][1] = mn1;
#pragma unroll
            for (int jn = 0; jn < 8; jn++) {
                o[jn][0] *= alpha0; o[jn][1] *= alpha0;
                o[jn][2] *= alpha1; o[jn][3] *= alpha1;
            }
            int pr = (t == 0) ? prow0 : prow1;
#pragma unroll
            for (int jn = 0; jn < 8; jn++) {
                uint32_t* p0 = &sP[pr * LDP2 + 8 * jn + 2 * c4];
                p0[0] = f2tf32(s[jn][0]);
                p0[1] = f2tf32(s[jn][1]);
                uint32_t* p1 = &sP[(pr + 8) * LDP2 + 8 * jn + 2 * c4];
                p1[0] = f2tf32(s[jn][2]);
                p1[1] = f2tf32(s[jn][3]);
            }
        }
        __syncwarp();

        // ---- O += P V (P A-frags via ldmatrix; V scalar, bits direct) ----
#pragma unroll
        for (int kk = 0; kk < 8; kk++) {
            uint32_t ap0[4], ap1[4];
            ldsm_x4(ap0[0], ap0[1], ap0[2], ap0[3],
                    paddr0 + (uint32_t)(kk * 32));
            ldsm_x4(ap1[0], ap1[1], ap1[2], ap1[3],
                    paddr1 + (uint32_t)(kk * 32));
#pragma unroll
            for (int jn = 0; jn < 8; jn++) {
                uint32_t b0 = sVu[(kk * 8 + c4) * LDV2 + 8 * jn + r8];
                uint32_t b1 = sVu[(kk * 8 + c4 + 4) * LDV2 + 8 * jn + r8];
                mma_tf32_16n8k8(o0[jn], ap0, b0, b1);
                mma_tf32_16n8k8(o1[jn], ap1, b0, b1);
            }
        }
        __syncwarp();
    }

#pragma unroll
    for (int t = 0; t < 2; t++) {
        float (*o)[4] = (t == 0) ? o0 : o1;
        float inv0 = 1.0f / lrow[t][0], inv1 = 1.0f / lrow[t][1];
        int row0 = q0 + wr + 16 * t + r8;
        int row1 = row0 + 8;
        size_t g0 = ((size_t)b * S_ + row0) * D_ + h * DK_;
        size_t g1 = ((size_t)b * S_ + row1) * D_ + h * DK_;
#pragma unroll
        for (int jn = 0; jn < 8; jn++) {
            int col = 8 * jn + 2 * c4;
            *(float2*)&g_ctx[g0 + col] = make_float2(o[jn][0] * inv0, o[jn][1] * inv0);
            *(float2*)&g_ctx[g1 + col] = make_float2(o[jn][2] * inv1, o[jn][3] * inv1);
        }
    }
}

// ---------------------------------------------------------------------------
// Launch
// ---------------------------------------------------------------------------
extern "C" void kernel_launch(void* const* d_in, const int* in_sizes, int n_in,
                              void* d_out, int out_size)
{
    const float* Q  = (const float*)d_in[0];
    const float* K  = (const float*)d_in[1];
    const float* V  = (const float*)d_in[2];
    const float* Wq = (const float*)d_in[3];
    const float* bq = (const float*)d_in[4];
    const float* Wk = (const float*)d_in[5];
    const float* bk = (const float*)d_in[6];
    const float* Wv = (const float*)d_in[7];
    const float* bv = (const float*)d_in[8];
    const float* Wo = (const float*)d_in[9];
    const float* bo = (const float*)d_in[10];
    float* out = (float*)d_out;

    cudaFuncSetAttribute(flash_tf32,
                         cudaFuncAttributeMaxDynamicSharedMemorySize, FSMEM);

    dim3 ggrid(D_ / 128, M_ / 128);   // (8, 64)
    gemm_tf32<<<ggrid, 256>>>(Q, Wq, bq, nullptr, 0);
    gemm_tf32<<<ggrid, 256>>>(K, Wk, bk, nullptr, 1);
    gemm_tf32<<<ggrid, 256>>>(V, Wv, bv, nullptr, 2);

    flash_tf32<<<dim3(S_ / 256, H_, B_), 256, FSMEM>>>();

    gemm_tf32<<<ggrid, 256>>>(nullptr, Wo, bo, out, 3);
}

// round 11
// speedup vs baseline: 1.3246x; 1.2459x over previous
#include <cuda_runtime.h>
#include <cuda_fp16.h>
#include <cstdint>
#include <math.h>

// Problem constants
constexpr int B_  = 4;
constexpr int S_  = 2048;
constexpr int D_  = 1024;
constexpr int H_  = 16;
constexpr int DK_ = 64;
constexpr int M_  = B_ * S_;   // 8192

// Scratch (device globals — no allocation allowed)
// Q/K/V now stored as fp16 (produced by proj epilogue, consumed by flash).
__device__ __half g_qh[(size_t)B_ * H_ * S_ * DK_];   // [B,H,S,DK]
__device__ __half g_kh[(size_t)B_ * H_ * S_ * DK_];
__device__ __half g_vh[(size_t)B_ * H_ * S_ * DK_];
__device__ float  g_ctx[(size_t)B_ * S_ * D_];        // [B,S,D] fp32

// ---------------------------------------------------------------------------
// helpers (all non-suffixed PTX: works under generic sm_103 target)
// ---------------------------------------------------------------------------
__device__ __forceinline__ uint32_t f2tf32(float f) {
    uint32_t r;
    asm("cvt.rna.tf32.f32 %0, %1;" : "=r"(r) : "f"(f));
    return r;
}

__device__ __forceinline__ void mma_tf32_16n8k8(float* c, const uint32_t* a,
                                                uint32_t b0, uint32_t b1) {
    asm volatile(
        "mma.sync.aligned.m16n8k8.row.col.f32.tf32.tf32.f32 "
        "{%0,%1,%2,%3}, {%4,%5,%6,%7}, {%8,%9}, {%0,%1,%2,%3};"
        : "+f"(c[0]), "+f"(c[1]), "+f"(c[2]), "+f"(c[3])
        : "r"(a[0]), "r"(a[1]), "r"(a[2]), "r"(a[3]), "r"(b0), "r"(b1));
}

__device__ __forceinline__ void mma_f16_16n8k16(float* c, const uint32_t* a,
                                                uint32_t b0, uint32_t b1) {
    asm volatile(
        "mma.sync.aligned.m16n8k16.row.col.f32.f16.f16.f32 "
        "{%0,%1,%2,%3}, {%4,%5,%6,%7}, {%8,%9}, {%0,%1,%2,%3};"
        : "+f"(c[0]), "+f"(c[1]), "+f"(c[2]), "+f"(c[3])
        : "r"(a[0]), "r"(a[1]), "r"(a[2]), "r"(a[3]), "r"(b0), "r"(b1));
}

__device__ __forceinline__ uint32_t smem_u32(const void* p) {
    uint32_t a;
    asm("{ .reg .u64 t; cvta.to.shared.u64 t, %1; cvt.u32.u64 %0, t; }"
        : "=r"(a) : "l"(p));
    return a;
}
__device__ __forceinline__ void cp_async16(uint32_t saddr, const void* g) {
    asm volatile("cp.async.ca.shared.global [%0], [%1], 16;"
                 :: "r"(saddr), "l"(g));
}
#define CP_COMMIT() asm volatile("cp.async.commit_group;" ::: "memory")
#define CP_WAIT0()  asm volatile("cp.async.wait_group 0;" ::: "memory")
#define CP_WAIT1()  asm volatile("cp.async.wait_group 1;" ::: "memory")

__device__ __forceinline__ void ldsm_x4(uint32_t& r0, uint32_t& r1,
                                        uint32_t& r2, uint32_t& r3,
                                        uint32_t addr) {
    asm volatile("ldmatrix.sync.aligned.m8n8.x4.shared.b16 {%0,%1,%2,%3}, [%4];"
                 : "=r"(r0), "=r"(r1), "=r"(r2), "=r"(r3) : "r"(addr));
}
__device__ __forceinline__ void ldsm_x4_trans(uint32_t& r0, uint32_t& r1,
                                              uint32_t& r2, uint32_t& r3,
                                              uint32_t addr) {
    asm volatile("ldmatrix.sync.aligned.m8n8.x4.trans.shared.b16 {%0,%1,%2,%3}, [%4];"
                 : "=r"(r0), "=r"(r1), "=r"(r2), "=r"(r3) : "r"(addr));
}

// ---------------------------------------------------------------------------
// TF32 tensor-core GEMM (R4 core, proven). Epilogue for which<3 now stores
// fp16 Q/K/V (same 10-bit mantissa as tf32 -> same quantization error).
// which==3 reads g_ctx (device-side) and writes fp32 dst.
// ---------------------------------------------------------------------------
constexpr int BK  = 16;
constexpr int LDA = 20;

__global__ __launch_bounds__(256, 2) void gemm_tf32(
    const float* __restrict__ X, const float* __restrict__ W,
    const float* __restrict__ bias, float* __restrict__ dst, int which)
{
    __shared__ uint32_t As[2][128 * LDA];
    __shared__ uint32_t Bs[2][128 * LDA];

    const int tid = threadIdx.x;
    const int wid = tid >> 5;
    const int lane = tid & 31;
    const int m0 = blockIdx.y * 128;
    const int n0 = blockIdx.x * 128;
    const int warp_m = (wid & 3) * 32;
    const int warp_n = (wid >> 2) * 64;

    const float* Xin = (which == 3) ? (const float*)g_ctx : X;

    const int r0 = tid >> 2;
    const int kq = (tid & 3) * 4;

    const float* gA = Xin + (size_t)m0 * D_;
    const float* gB = W + (size_t)n0 * D_;

    float acc[2][8][4];
#pragma unroll
    for (int i = 0; i < 2; i++)
#pragma unroll
        for (int j = 0; j < 8; j++)
#pragma unroll
            for (int r = 0; r < 4; r++) acc[i][j][r] = 0.f;

    float4 pa0, pa1, pb0, pb1;

    auto ldg = [&](int t) {
        const float* a = gA + (size_t)r0 * D_ + t * BK + kq;
        pa0 = *(const float4*)a;
        pa1 = *(const float4*)(a + (size_t)64 * D_);
        const float* b = gB + (size_t)r0 * D_ + t * BK + kq;
        pb0 = *(const float4*)b;
        pb1 = *(const float4*)(b + (size_t)64 * D_);
    };
    auto sts = [&](int s) {
        uint32_t* A = As[s];
        uint32_t* Bsh = Bs[s];
        int o0 = r0 * LDA + kq;
        int o1 = (r0 + 64) * LDA + kq;
        A[o0 + 0] = f2tf32(pa0.x); A[o0 + 1] = f2tf32(pa0.y);
        A[o0 + 2] = f2tf32(pa0.z); A[o0 + 3] = f2tf32(pa0.w);
        A[o1 + 0] = f2tf32(pa1.x); A[o1 + 1] = f2tf32(pa1.y);
        A[o1 + 2] = f2tf32(pa1.z); A[o1 + 3] = f2tf32(pa1.w);
        Bsh[o0 + 0] = f2tf32(pb0.x); Bsh[o0 + 1] = f2tf32(pb0.y);
        Bsh[o0 + 2] = f2tf32(pb0.z); Bsh[o0 + 3] = f2tf32(pb0.w);
        Bsh[o1 + 0] = f2tf32(pb1.x); Bsh[o1 + 1] = f2tf32(pb1.y);
        Bsh[o1 + 2] = f2tf32(pb1.z); Bsh[o1 + 3] = f2tf32(pb1.w);
    };

    ldg(0);
    sts(0);
    __syncthreads();

    const int r8 = lane >> 2;
    const int c4 = lane & 3;

    for (int t = 0; t < D_ / BK; t++) {
        int s = t & 1;
        if (t < D_ / BK - 1) ldg(t + 1);

#pragma unroll
        for (int ks = 0; ks < 2; ks++) {
            const int kk = ks * 8;
            uint32_t a[2][4], b[8][2];
#pragma unroll
            for (int im = 0; im < 2; im++) {
                int mr = warp_m + 16 * im + r8;
                a[im][0] = As[s][mr * LDA + kk + c4];
                a[im][1] = As[s][(mr + 8) * LDA + kk + c4];
                a[im][2] = As[s][mr * LDA + kk + c4 + 4];
                a[im][3] = As[s][(mr + 8) * LDA + kk + c4 + 4];
            }
#pragma unroll
            for (int jn = 0; jn < 8; jn++) {
                int nr = warp_n + 8 * jn + r8;
                b[jn][0] = Bs[s][nr * LDA + kk + c4];
                b[jn][1] = Bs[s][nr * LDA + kk + c4 + 4];
            }
#pragma unroll
            for (int im = 0; im < 2; im++)
#pragma unroll
                for (int jn = 0; jn < 8; jn++)
                    mma_tf32_16n8k8(acc[im][jn], a[im], b[jn][0], b[jn][1]);
        }

        if (t < D_ / BK - 1) sts(s ^ 1);
        __syncthreads();
    }

    const int c2 = (lane & 3) * 2;
#pragma unroll
    for (int im = 0; im < 2; im++) {
#pragma unroll
        for (int jn = 0; jn < 8; jn++) {
            int n = n0 + warp_n + 8 * jn + c2;
            float bx = bias[n], by = bias[n + 1];
            int mA = m0 + warp_m + 16 * im + r8;
            int mB = mA + 8;
            float2 v0 = make_float2(acc[im][jn][0] + bx, acc[im][jn][1] + by);
            float2 v1 = make_float2(acc[im][jn][2] + bx, acc[im][jn][3] + by);
            if (which < 3) {
                __half* outh = (which == 0) ? g_qh : (which == 1) ? g_kh : g_vh;
                __half2 h0 = __floats2half2_rn(v0.x, v0.y);
                __half2 h1 = __floats2half2_rn(v1.x, v1.y);
                int h = n >> 6, dk = n & 63;
                int bA = mA >> 11, sA = mA & (S_ - 1);
                int bB = mB >> 11, sB = mB & (S_ - 1);
                *(__half2*)&outh[(((size_t)(bA * H_ + h) * S_ + sA) << 6) + dk] = h0;
                *(__half2*)&outh[(((size_t)(bB * H_ + h) * S_ + sB) << 6) + dk] = h1;
            } else {
                *(float2*)&dst[(size_t)mA * D_ + n] = v0;
                *(float2*)&dst[(size_t)mB * D_ + n] = v1;
            }
        }
    }
}

// ---------------------------------------------------------------------------
// Flash attention v6: fp16 m16n8k16 mma (2x FLOP/instr, 1/2 smem traffic).
// BQ=256, 8 warps, 2 m-tiles/warp (fragment sharing kept). cp.async 2-stage
// K/V. All fragments via ldmatrix: Q/P non-trans A-frags, K non-trans
// B-frags, V .trans B-frags. Row stride 144B (16B-aligned, ldsm
// conflict-free). fp32 accumulate + fp32 softmax unchanged.
// ---------------------------------------------------------------------------
constexpr int LDH    = 72;            // halves per row (144 B)
constexpr int QBYTES = 256 * 144;     // 36864
constexpr int KSTAGE = 64 * 144;      // 9216
constexpr int VSTAGE = 64 * 144;      // 9216
constexpr int PBYTES = 256 * 144;     // 36864
constexpr int FSMEM  = QBYTES + 2 * KSTAGE + 2 * VSTAGE + PBYTES;  // 110592

__global__ __launch_bounds__(256, 1) void flash_f16()
{
    extern __shared__ char smc[];
    char* sQ = smc;
    char* sK = sQ + QBYTES;
    char* sV = sK + 2 * KSTAGE;
    char* sP = sV + 2 * VSTAGE;

    const uint32_t sqb = smem_u32(sQ);
    const uint32_t skb = smem_u32(sK);
    const uint32_t svb = smem_u32(sV);
    const uint32_t spb = smem_u32(sP);
    __half* sPh = (__half*)sP;

    const int tid = threadIdx.x;
    const int wid = tid >> 5;
    const int lane = tid & 31;
    const int r8 = lane >> 2;
    const int c4 = lane & 3;
    const int lm = lane >> 3;
    const int lr7 = lane & 7;

    // ldsm per-lane address offsets (bytes)
    // A-frag (Q, P): matrices (rows0-7,k0),(rows8-15,k0),(rows0-7,k8),(rows8-15,k8)
    const uint32_t laneA =
        (uint32_t)(((lm & 1) * 8 + lr7) * 144 + (lm >> 1) * 16);
    // K B-frag: matrices (keys0-7,k0),(keys0-7,k8),(keys8-15,k0),(keys8-15,k8)
    const uint32_t laneB =
        (uint32_t)(((lm >> 1) * 8 + lr7) * 144 + (lm & 1) * 16);
    // V trans B-frag: matrices (keys0-7,n0),(keys8-15,n0),(keys0-7,n8),(keys8-15,n8)
    const uint32_t laneV =
        (uint32_t)(((lm & 1) * 8 + lr7) * 144 + (lm >> 1) * 16);

    const int q0 = blockIdx.x * 256;
    const int h = blockIdx.y;
    const int b = blockIdx.z;
    const size_t base = (size_t)(b * H_ + h) * S_ * DK_;
    const __half* qg = g_qh + base + (size_t)q0 * DK_;
    const __half* kg = g_kh + base;
    const __half* vg = g_vh + base;

    const int wr = wid * 32;

    // ---- async fills ----
    auto issue_chunk = [&](int kb, int st) {
#pragma unroll
        for (int i = 0; i < 2; i++) {
            int idx = tid + i * 256;          // 0..511
            int row = idx >> 3;               // key 0..63
            int c16 = (idx & 7) * 16;         // byte col (16B chunks)
            cp_async16(skb + (uint32_t)(st * KSTAGE + row * 144) + c16,
                       kg + (size_t)(kb + row) * DK_ + (idx & 7) * 8);
            cp_async16(svb + (uint32_t)(st * VSTAGE + row * 144) + c16,
                       vg + (size_t)(kb + row) * DK_ + (idx & 7) * 8);
        }
        CP_COMMIT();
    };

    // Q fill (whole 256x64 tile, once)
#pragma unroll
    for (int i = 0; i < 8; i++) {
        int idx = tid + i * 256;              // 0..2047
        int row = idx >> 3;                   // 0..255
        int c16 = (idx & 7) * 16;
        cp_async16(sqb + (uint32_t)(row * 144) + c16,
                   qg + (size_t)row * DK_ + (idx & 7) * 8);
    }
    CP_COMMIT();
    issue_chunk(0, 0);

    CP_WAIT1();          // Q group done (chunk0 still in flight)
    __syncthreads();

    // ---- Q A-fragments, pre-scaled by 0.125 (exact power-of-2 in fp16) ----
    uint32_t aq[2][4][4];
    {
        const __half2 hs = __half2half2(__float2half_rn(0.125f));
#pragma unroll
        for (int t = 0; t < 2; t++) {
#pragma unroll
            for (int kc = 0; kc < 4; kc++) {
                uint32_t addr = sqb + (uint32_t)((wr + 16 * t) * 144 + kc * 32) + laneA;
                ldsm_x4(aq[t][kc][0], aq[t][kc][1], aq[t][kc][2], aq[t][kc][3], addr);
#pragma unroll
                for (int r = 0; r < 4; r++) {
                    __half2 v = *(__half2*)&aq[t][kc][r];
                    v = __hmul2(v, hs);
                    aq[t][kc][r] = *(uint32_t*)&v;
                }
            }
        }
    }

    float mrow[2][2], lrow[2][2];
    float o0[8][4], o1[8][4];
#pragma unroll
    for (int t = 0; t < 2; t++) {
        mrow[t][0] = mrow[t][1] = -1e30f;
        lrow[t][0] = lrow[t][1] = 0.f;
    }
#pragma unroll
    for (int j = 0; j < 8; j++)
#pragma unroll
        for (int r = 0; r < 4; r++) { o0[j][r] = 0.f; o1[j][r] = 0.f; }

    const uint32_t paddr0 = spb + (uint32_t)(wr * 144) + laneA;         // tile0
    const uint32_t paddr1 = spb + (uint32_t)((wr + 16) * 144) + laneA;  // tile1

    for (int c = 0; c < S_ / 64; c++) {
        const int st = c & 1;
        CP_WAIT0();
        __syncthreads();
        if (c + 1 < S_ / 64) issue_chunk((c + 1) * 64, st ^ 1);

        const uint32_t skc = skb + (uint32_t)(st * KSTAGE) + laneB;
        const uint32_t svc = svb + (uint32_t)(st * VSTAGE) + laneV;

        // ---- S = Q K^T (fp16 k16; 4 k-chunks x 4 jn-pairs) ----
        float s0[8][4], s1[8][4];
#pragma unroll
        for (int j = 0; j < 8; j++)
#pragma unroll
            for (int r = 0; r < 4; r++) { s0[j][r] = 0.f; s1[j][r] = 0.f; }

#pragma unroll
        for (int kc = 0; kc < 4; kc++) {
#pragma unroll
            for (int jnp = 0; jnp < 4; jnp++) {
                uint32_t k0, k1, k2, k3;
                ldsm_x4(k0, k1, k2, k3,
                        skc + (uint32_t)(jnp * 16 * 144 + kc * 32));
                mma_f16_16n8k16(s0[2 * jnp], aq[0][kc], k0, k1);
                mma_f16_16n8k16(s1[2 * jnp], aq[1][kc], k0, k1);
                mma_f16_16n8k16(s0[2 * jnp + 1], aq[0][kc], k2, k3);
                mma_f16_16n8k16(s1[2 * jnp + 1], aq[1][kc], k2, k3);
            }
        }

        // ---- online softmax + stage P (fp16), per tile ----
#pragma unroll
        for (int t = 0; t < 2; t++) {
            float (*s)[4] = (t == 0) ? s0 : s1;
            float (*o)[4] = (t == 0) ? o0 : o1;
            float mx0 = -1e30f, mx1 = -1e30f;
#pragma unroll
            for (int jn = 0; jn < 8; jn++) {
                mx0 = fmaxf(mx0, fmaxf(s[jn][0], s[jn][1]));
                mx1 = fmaxf(mx1, fmaxf(s[jn][2], s[jn][3]));
            }
            mx0 = fmaxf(mx0, __shfl_xor_sync(0xffffffffu, mx0, 1));
            mx0 = fmaxf(mx0, __shfl_xor_sync(0xffffffffu, mx0, 2));
            mx1 = fmaxf(mx1, __shfl_xor_sync(0xffffffffu, mx1, 1));
            mx1 = fmaxf(mx1, __shfl_xor_sync(0xffffffffu, mx1, 2));
            float mn0 = fmaxf(mrow[t][0], mx0), mn1 = fmaxf(mrow[t][1], mx1);
            float alpha0 = __expf(mrow[t][0] - mn0);
            float alpha1 = __expf(mrow[t][1] - mn1);
            float sum0 = 0.f, sum1 = 0.f;
#pragma unroll
            for (int jn = 0; jn < 8; jn++) {
                s[jn][0] = __expf(s[jn][0] - mn0);
                s[jn][1] = __expf(s[jn][1] - mn0);
                s[jn][2] = __expf(s[jn][2] - mn1);
                s[jn][3] = __expf(s[jn][3] - mn1);
                sum0 += s[jn][0] + s[jn][1];
                sum1 += s[jn][2] + s[jn][3];
            }
            sum0 += __shfl_xor_sync(0xffffffffu, sum0, 1);
            sum0 += __shfl_xor_sync(0xffffffffu, sum0, 2);
            sum1 += __shfl_xor_sync(0xffffffffu, sum1, 1);
            sum1 += __shfl_xor_sync(0xffffffffu, sum1, 2);
            lrow[t][0] = lrow[t][0] * alpha0 + sum0;
            lrow[t][1] = lrow[t][1] * alpha1 + sum1;
            mrow[t][0] = mn0;
            mrow[t][1] = mn1;
#pragma unroll
            for (int jn = 0; jn < 8; jn++) {
                o[jn][0] *= alpha0; o[jn][1] *= alpha0;
                o[jn][2] *= alpha1; o[jn][3] *= alpha1;
            }
            int pr = wr + 16 * t + r8;
#pragma unroll
            for (int jn = 0; jn < 8; jn++) {
                *(__half2*)&sPh[pr * LDH + 8 * jn + 2 * c4] =
                    __floats2half2_rn(s[jn][0], s[jn][1]);
                *(__half2*)&sPh[(pr + 8) * LDH + 8 * jn + 2 * c4] =
                    __floats2half2_rn(s[jn][2], s[jn][3]);
            }
        }
        __syncwarp();

        // ---- O += P V (P A-frags ldsm; V B-frags ldsm.trans) ----
#pragma unroll
        for (int kc = 0; kc < 4; kc++) {
            uint32_t ap0[4], ap1[4];
            ldsm_x4(ap0[0], ap0[1], ap0[2], ap0[3],
                    paddr0 + (uint32_t)(kc * 32));
            ldsm_x4(ap1[0], ap1[1], ap1[2], ap1[3],
                    paddr1 + (uint32_t)(kc * 32));
#pragma unroll
            for (int jnp = 0; jnp < 4; jnp++) {
                uint32_t v0, v1, v2, v3;
                ldsm_x4_trans(v0, v1, v2, v3,
                              svc + (uint32_t)(kc * 16 * 144 + jnp * 32));
                mma_f16_16n8k16(o0[2 * jnp], ap0, v0, v1);
                mma_f16_16n8k16(o1[2 * jnp], ap1, v0, v1);
                mma_f16_16n8k16(o0[2 * jnp + 1], ap0, v2, v3);
                mma_f16_16n8k16(o1[2 * jnp + 1], ap1, v2, v3);
            }
        }
        __syncwarp();
    }

    // ---- epilogue: normalize + write ctx [B,S,D] fp32 ----
#pragma unroll
    for (int t = 0; t < 2; t++) {
        float (*o)[4] = (t == 0) ? o0 : o1;
        float inv0 = 1.0f / lrow[t][0], inv1 = 1.0f / lrow[t][1];
        int row0 = q0 + wr + 16 * t + r8;
        int row1 = row0 + 8;
        size_t g0 = ((size_t)b * S_ + row0) * D_ + h * DK_;
        size_t g1 = ((size_t)b * S_ + row1) * D_ + h * DK_;
#pragma unroll
        for (int jn = 0; jn < 8; jn++) {
            int col = 8 * jn + 2 * c4;
            *(float2*)&g_ctx[g0 + col] = make_float2(o[jn][0] * inv0, o[jn][1] * inv0);
            *(float2*)&g_ctx[g1 + col] = make_float2(o[jn][2] * inv1, o[jn][3] * inv1);
        }
    }
}

// ---------------------------------------------------------------------------
// Launch
// ---------------------------------------------------------------------------
extern "C" void kernel_launch(void* const* d_in, const int* in_sizes, int n_in,
                              void* d_out, int out_size)
{
    const float* Q  = (const float*)d_in[0];
    const float* K  = (const float*)d_in[1];
    const float* V  = (const float*)d_in[2];
    const float* Wq = (const float*)d_in[3];
    const float* bq = (const float*)d_in[4];
    const float* Wk = (const float*)d_in[5];
    const float* bk = (const float*)d_in[6];
    const float* Wv = (const float*)d_in[7];
    const float* bv = (const float*)d_in[8];
    const float* Wo = (const float*)d_in[9];
    const float* bo = (const float*)d_in[10];
    float* out = (float*)d_out;

    cudaFuncSetAttribute(flash_f16,
                         cudaFuncAttributeMaxDynamicSharedMemorySize, FSMEM);

    dim3 ggrid(D_ / 128, M_ / 128);   // (8, 64)
    gemm_tf32<<<ggrid, 256>>>(Q, Wq, bq, nullptr, 0);
    gemm_tf32<<<ggrid, 256>>>(K, Wk, bk, nullptr, 1);
    gemm_tf32<<<ggrid, 256>>>(V, Wv, bv, nullptr, 2);

    flash_f16<<<dim3(S_ / 256, H_, B_), 256, FSMEM>>>();

    gemm_tf32<<<ggrid, 256>>>(nullptr, Wo, bo, out, 3);
}